// round 10
// baseline (speedup 1.0000x reference)
#include <cuda_runtime.h>
#include <cuda_bf16.h>
#include <math.h>
#include <stdint.h>

#define NN 100000
#define NE 3200000
#define NF 512
#define NH 256
#define NC 16
#define NLAYER 8

// ---------------- device scratch (allocation-free rule: __device__ globals) ----
__device__ float g_h  [(size_t)NN * NH];
__device__ float g_h0 [(size_t)NN * NH];
__device__ float g_sup[(size_t)NN * NH];
__device__ int   g_rowptr[NN + 1];
__device__ int   g_cnt[NN];
__device__ int2  g_edge[NE];     // packed (src, weight-bits)
// pre-transposed, bf16 hi/lo split weights:
// conv W' = theta*W + (1-theta)*I  -> [8][N=256][K=256];  fc0 [N=256][K=512]
__device__ __nv_bfloat16 g_wth[(size_t)NLAYER * NH * NH];
__device__ __nv_bfloat16 g_wtl[(size_t)NLAYER * NH * NH];
__device__ __nv_bfloat16 g_w0h[(size_t)NH * NF];
__device__ __nv_bfloat16 g_w0l[(size_t)NH * NF];

struct Thetas { float t[NLAYER]; };

// ---------------- CSR build ---------------------------------------------------
__global__ void zero_cnt_kernel(int* __restrict__ cnt) {
    int i = blockIdx.x * blockDim.x + threadIdx.x;
    if (i < NN) cnt[i] = 0;
}

__global__ void hist_kernel(const int* __restrict__ dst, int* __restrict__ cnt) {
    int e = blockIdx.x * blockDim.x + threadIdx.x;
    if (e < NE) atomicAdd(&cnt[dst[e]], 1);
}

__global__ __launch_bounds__(1024) void scan_kernel(int* __restrict__ cnt,
                                                    int* __restrict__ rowptr) {
    const int tid  = threadIdx.x;
    const int lane = tid & 31;
    const int wid  = tid >> 5;
    __shared__ int wsum[32];
    int carry = 0;
    for (int base = 0; base < NN; base += 1024) {
        int i = base + tid;
        int v = (i < NN) ? cnt[i] : 0;
        int incl = v;
#pragma unroll
        for (int off = 1; off < 32; off <<= 1) {
            int t = __shfl_up_sync(0xffffffffu, incl, off);
            if (lane >= off) incl += t;
        }
        if (lane == 31) wsum[wid] = incl;
        __syncthreads();
        if (wid == 0) {
            int s = wsum[lane];
#pragma unroll
            for (int off = 1; off < 32; off <<= 1) {
                int t = __shfl_up_sync(0xffffffffu, s, off);
                if (lane >= off) s += t;
            }
            wsum[lane] = s;
        }
        __syncthreads();
        int woff = (wid > 0) ? wsum[wid - 1] : 0;
        int excl = carry + woff + (incl - v);
        if (i < NN) { rowptr[i] = excl; cnt[i] = excl; }
        int total = wsum[31];
        __syncthreads();
        carry += total;
    }
    if (tid == 0) rowptr[NN] = carry;
}

__global__ void scatter_kernel(const int* __restrict__ src,
                               const int* __restrict__ dst,
                               const float* __restrict__ w,
                               int* __restrict__ cur,
                               int2* __restrict__ edge) {
    int e = blockIdx.x * blockDim.x + threadIdx.x;
    if (e < NE) {
        int d = dst[e];
        int p = atomicAdd(&cur[d], 1);
        edge[p] = make_int2(src[e], __float_as_int(w[e]));
    }
}

// ---------------- weight transpose + residual fold + bf16 hi/lo split ----------
__global__ void prep_w_kernel(const float* __restrict__ w0,
                              const float* __restrict__ convw,
                              __nv_bfloat16* __restrict__ w0h,
                              __nv_bfloat16* __restrict__ w0l,
                              __nv_bfloat16* __restrict__ wth,
                              __nv_bfloat16* __restrict__ wtl,
                              Thetas th) {
    int i = blockIdx.x * blockDim.x + threadIdx.x;
    if (i < NH * NF) {           // w0^T: [n][k], k stride 512
        int n = i >> 9, k = i & 511;
        float f = w0[(size_t)k * NH + n];
        __nv_bfloat16 h = __float2bfloat16(f);
        w0h[i] = h;
        w0l[i] = __float2bfloat16(f - __bfloat162float(h));
    }
    if (i < NLAYER * NH * NH) {  // W'^T: [l][n][k];  W' = theta*W + (1-theta)*I
        int l = i >> 16, nk = i & 65535, n = nk >> 8, k = nk & 255;
        float theta = th.t[l];
        float f = theta * convw[(size_t)l * 65536 + (size_t)k * NH + n];
        if (k == n) f += 1.0f - theta;
        __nv_bfloat16 h = __float2bfloat16(f);
        wth[i] = h;
        wtl[i] = __float2bfloat16(f - __bfloat162float(h));
    }
}

// ---------------- SpMM: warp per row, half the features per pass ---------------
__device__ __forceinline__ void fmav(float4& a, float w, const float4& v) {
    a.x = fmaf(w, v.x, a.x); a.y = fmaf(w, v.y, a.y);
    a.z = fmaf(w, v.z, a.z); a.w = fmaf(w, v.w, a.w);
}

__global__ __launch_bounds__(256) void spmm_half_kernel(
    const int* __restrict__ rowptr, const int2* __restrict__ edge,
    const float* __restrict__ h, const float* __restrict__ h0,
    float* __restrict__ sup, int col4) {
    const int warp = threadIdx.x >> 5;
    const int lane = threadIdx.x & 31;
    const int row  = blockIdx.x * 8 + warp;
    if (row >= NN) return;
    int e = rowptr[row];
    const int end = rowptr[row + 1];
    const float4* hp = (const float4*)h + col4 + lane;
    float4 acc = make_float4(0.f, 0.f, 0.f, 0.f);
    for (; e + 4 <= end; e += 4) {
        int2 r0 = __ldg(edge + e),     r1 = __ldg(edge + e + 1);
        int2 r2 = __ldg(edge + e + 2), r3 = __ldg(edge + e + 3);
        float4 v0 = hp[(size_t)(r0.x * 64)];
        float4 v1 = hp[(size_t)(r1.x * 64)];
        float4 v2 = hp[(size_t)(r2.x * 64)];
        float4 v3 = hp[(size_t)(r3.x * 64)];
        fmav(acc, __int_as_float(r0.y), v0);
        fmav(acc, __int_as_float(r1.y), v1);
        fmav(acc, __int_as_float(r2.y), v2);
        fmav(acc, __int_as_float(r3.y), v3);
    }
    for (; e < end; ++e) {
        int2 r = __ldg(edge + e);
        fmav(acc, __int_as_float(r.y), hp[(size_t)(r.x * 64)]);
    }
    const size_t oi = (size_t)row * 64 + col4 + lane;
    float4 r = __ldcs((const float4*)h0 + oi);
    float4 o;
    o.x = fmaf(0.9f, acc.x, 0.1f * r.x);
    o.y = fmaf(0.9f, acc.y, 0.1f * r.y);
    o.z = fmaf(0.9f, acc.z, 0.1f * r.z);
    o.w = fmaf(0.9f, acc.w, 0.1f * r.w);
    __stcs((float4*)sup + oi, o);
}

// ---------------- mma.sync bf16 GEMM: 128x128 tile, hi/lo split (3 MMAs) ------
// mode 0: h = h0 = relu(A@B + bias)       (A = x, K = 512)
// mode 1: h = relu(A@B' + h)              (A = sup, K = 256, B' has residual folded)
// B pre-transposed K-major bf16: Bh/Bl[n][k], row stride K.
#define BM 128
#define BN 128
#define BKC 64
// smem: 4 tiles of 128 rows x 128B (SW128-swizzled)
#define SA_H 0
#define SA_L 16384
#define SB_H 32768
#define SB_L 49152
#define GEMM_SMEM 65536

__device__ __forceinline__ uint32_t smem_u32(const void* p) {
    uint32_t a;
    asm("{ .reg .u64 t; cvta.to.shared.u64 t, %1; cvt.u32.u64 %0, t; }" : "=r"(a) : "l"(p));
    return a;
}

__device__ __forceinline__ void ldsm_x4(uint32_t* r, uint32_t addr) {
    asm volatile("ldmatrix.sync.aligned.m8n8.x4.shared.b16 {%0,%1,%2,%3}, [%4];"
                 : "=r"(r[0]), "=r"(r[1]), "=r"(r[2]), "=r"(r[3]) : "r"(addr));
}
__device__ __forceinline__ void ldsm_x2(uint32_t* r, uint32_t addr) {
    asm volatile("ldmatrix.sync.aligned.m8n8.x2.shared.b16 {%0,%1}, [%2];"
                 : "=r"(r[0]), "=r"(r[1]) : "r"(addr));
}
__device__ __forceinline__ void mma_bf16(float* d, const uint32_t* a, const uint32_t* b) {
    asm volatile("mma.sync.aligned.m16n8k16.row.col.f32.bf16.bf16.f32 "
                 "{%0,%1,%2,%3}, {%4,%5,%6,%7}, {%8,%9}, {%0,%1,%2,%3};"
                 : "+f"(d[0]), "+f"(d[1]), "+f"(d[2]), "+f"(d[3])
                 : "r"(a[0]), "r"(a[1]), "r"(a[2]), "r"(a[3]), "r"(b[0]), "r"(b[1]));
}

__global__ __launch_bounds__(256, 1) void gemm_mma_kernel(
    const float* __restrict__ A, int M, int K,
    const __nv_bfloat16* __restrict__ Bh, const __nv_bfloat16* __restrict__ Bl,
    const float* __restrict__ bias,
    float* __restrict__ hout, float* __restrict__ h0out,
    int mode) {
    extern __shared__ char smem[];
    const uint32_t sb = smem_u32(smem);
    const int tid  = threadIdx.x;
    const int warp = tid >> 5;
    const int lane = tid & 31;
    const int wm = warp & 1;    // M warp: 0..1 -> 64 rows each
    const int wn = warp >> 1;   // N warp: 0..3 -> 32 cols each
    // N-tile fastest-varying (blockIdx.x) so the two N-tiles sharing an A
    // row-block are adjacent CTAs -> second A read hits L2.
    const int rowBase = blockIdx.y * BM;
    const int nBase   = blockIdx.x * BN;

    float acc[4][4][4];
#pragma unroll
    for (int i = 0; i < 4; i++)
#pragma unroll
        for (int j = 0; j < 4; j++)
#pragma unroll
            for (int r = 0; r < 4; r++) acc[i][j][r] = 0.f;

    // fill indices
    const int frow = tid >> 3;   // 0..31 (+32*j)
    const int fc8  = tid & 7;    // 8-element (16B bf16 / 32B fp32) unit

    for (int kb = 0; kb < K; kb += BKC) {
        // ---- fill A: fp32 -> bf16 hi/lo split, SW128 swizzled ----
#pragma unroll
        for (int j = 0; j < 4; ++j) {
            int row = frow + 32 * j;
            int grow = rowBase + row;
            float4 v0 = make_float4(0.f, 0.f, 0.f, 0.f), v1 = v0;
            if (grow < M) {
                const float* ap = A + (size_t)grow * K + kb + fc8 * 8;
                v0 = *(const float4*)ap;
                v1 = *(const float4*)(ap + 4);
            }
            __nv_bfloat162 h01 = __floats2bfloat162_rn(v0.x, v0.y);
            __nv_bfloat162 h23 = __floats2bfloat162_rn(v0.z, v0.w);
            __nv_bfloat162 h45 = __floats2bfloat162_rn(v1.x, v1.y);
            __nv_bfloat162 h67 = __floats2bfloat162_rn(v1.z, v1.w);
            float2 f01 = __bfloat1622float2(h01);
            float2 f23 = __bfloat1622float2(h23);
            float2 f45 = __bfloat1622float2(h45);
            float2 f67 = __bfloat1622float2(h67);
            __nv_bfloat162 l01 = __floats2bfloat162_rn(v0.x - f01.x, v0.y - f01.y);
            __nv_bfloat162 l23 = __floats2bfloat162_rn(v0.z - f23.x, v0.w - f23.y);
            __nv_bfloat162 l45 = __floats2bfloat162_rn(v1.x - f45.x, v1.y - f45.y);
            __nv_bfloat162 l67 = __floats2bfloat162_rn(v1.z - f67.x, v1.w - f67.y);
            uint32_t off = (uint32_t)(row * 128 + ((fc8 ^ (row & 7)) << 4));
            uint4 uh, ul;
            uh.x = *(uint32_t*)&h01; uh.y = *(uint32_t*)&h23;
            uh.z = *(uint32_t*)&h45; uh.w = *(uint32_t*)&h67;
            ul.x = *(uint32_t*)&l01; ul.y = *(uint32_t*)&l23;
            ul.z = *(uint32_t*)&l45; ul.w = *(uint32_t*)&l67;
            *(uint4*)(smem + SA_H + off) = uh;
            *(uint4*)(smem + SA_L + off) = ul;
        }
        // ---- fill B: pre-split bf16 [n][K], SW128 swizzled ----
#pragma unroll
        for (int j = 0; j < 4; ++j) {
            int n = frow + 32 * j;
            size_t gi = (size_t)(nBase + n) * K + kb + fc8 * 8;
            uint32_t off = (uint32_t)(n * 128 + ((fc8 ^ (n & 7)) << 4));
            *(uint4*)(smem + SB_H + off) = *(const uint4*)(Bh + gi);
            *(uint4*)(smem + SB_L + off) = *(const uint4*)(Bl + gi);
        }
        __syncthreads();

        // ---- compute: 4 k16 steps ----
#pragma unroll
        for (int ks = 0; ks < 4; ++ks) {
            const int u0 = ks * 2;
            uint32_t ah[4][4], al[4][4], bh[4][2], bl[4][2];
#pragma unroll
            for (int mt = 0; mt < 4; ++mt) {
                int row  = wm * 64 + mt * 16 + (lane & 15);
                int unit = u0 + (lane >> 4);
                uint32_t off = (uint32_t)(row * 128 + ((unit ^ (row & 7)) << 4));
                ldsm_x4(ah[mt], sb + SA_H + off);
                ldsm_x4(al[mt], sb + SA_L + off);
            }
#pragma unroll
            for (int nt = 0; nt < 4; ++nt) {
                int n    = wn * 32 + nt * 8 + (lane & 7);
                int unit = u0 + ((lane >> 3) & 1);
                uint32_t off = (uint32_t)(n * 128 + ((unit ^ (n & 7)) << 4));
                ldsm_x2(bh[nt], sb + SB_H + off);
                ldsm_x2(bl[nt], sb + SB_L + off);
            }
#pragma unroll
            for (int mt = 0; mt < 4; ++mt)
#pragma unroll
                for (int nt = 0; nt < 4; ++nt) {
                    mma_bf16(acc[mt][nt], ah[mt], bh[nt]);
                    mma_bf16(acc[mt][nt], ah[mt], bl[nt]);
                    mma_bf16(acc[mt][nt], al[mt], bh[nt]);
                }
        }
        __syncthreads();
    }

    // ---- epilogue ----
    const int r0 = rowBase + wm * 64 + (lane >> 2);
    const int c0 = nBase + wn * 32 + 2 * (lane & 3);
#pragma unroll
    for (int mt = 0; mt < 4; ++mt) {
#pragma unroll
        for (int half = 0; half < 2; ++half) {
            int grow = r0 + mt * 16 + half * 8;
            if (grow >= M) continue;
#pragma unroll
            for (int nt = 0; nt < 4; ++nt) {
                float d0 = acc[mt][nt][half * 2 + 0];
                float d1 = acc[mt][nt][half * 2 + 1];
                int gc = c0 + nt * 8;
                size_t gi = (size_t)grow * NH + gc;
                if (mode == 0) {
                    float v0 = fmaxf(d0 + __ldg(&bias[gc]),     0.f);
                    float v1 = fmaxf(d1 + __ldg(&bias[gc + 1]), 0.f);
                    float2 v = make_float2(v0, v1);
                    *(float2*)(hout  + gi) = v;
                    *(float2*)(h0out + gi) = v;
                } else {
                    float2 ho = *(const float2*)(hout + gi);
                    float v0 = fmaxf(d0 + ho.x, 0.f);
                    float v1 = fmaxf(d1 + ho.y, 0.f);
                    *(float2*)(hout + gi) = make_float2(v0, v1);
                }
            }
        }
    }
}

// ---------------- final fc + sigmoid ------------------------------------------
__global__ __launch_bounds__(128) void fc1_kernel(const float* __restrict__ h,
                                                  const float* __restrict__ w1,
                                                  const float* __restrict__ b1,
                                                  float* __restrict__ out) {
    __shared__ float ws[NH * NC];
    __shared__ float bs[NC];
    const int tid = threadIdx.x;
    for (int i = tid; i < NH * NC; i += 128) ws[i] = w1[i];
    if (tid < NC) bs[tid] = b1[tid];
    __syncthreads();
    const int col = tid & 15;
    const int r   = tid >> 4;
    const int row = blockIdx.x * 8 + r;
    if (row >= NN) return;
    const float* hr = h + (size_t)row * NH;
    float acc = 0.f;
#pragma unroll 4
    for (int k = 0; k < NH; k += 4) {
        float4 hv = *(const float4*)(hr + k);
        acc = fmaf(hv.x, ws[(k + 0) * NC + col], acc);
        acc = fmaf(hv.y, ws[(k + 1) * NC + col], acc);
        acc = fmaf(hv.z, ws[(k + 2) * NC + col], acc);
        acc = fmaf(hv.w, ws[(k + 3) * NC + col], acc);
    }
    acc += bs[col];
    out[(size_t)row * NC + col] = 1.0f / (1.0f + expf(-acc));
}

// ---------------- launch -------------------------------------------------------
extern "C" void kernel_launch(void* const* d_in, const int* in_sizes, int n_in,
                              void* d_out, int out_size) {
    const float* x     = (const float*)d_in[0];
    const int*   esrc  = (const int*)  d_in[1];
    const int*   edst  = (const int*)  d_in[2];
    const float* ew    = (const float*)d_in[3];
    const float* w0    = (const float*)d_in[4];
    const float* b0    = (const float*)d_in[5];
    const float* convw = (const float*)d_in[6];
    const float* w1    = (const float*)d_in[7];
    const float* b1    = (const float*)d_in[8];
    float* out = (float*)d_out;

    void *ph, *ph0, *psup, *prp, *pcnt, *pedge;
    void *pwth, *pwtl, *pw0h, *pw0l;
    cudaGetSymbolAddress(&ph,    g_h);
    cudaGetSymbolAddress(&ph0,   g_h0);
    cudaGetSymbolAddress(&psup,  g_sup);
    cudaGetSymbolAddress(&prp,   g_rowptr);
    cudaGetSymbolAddress(&pcnt,  g_cnt);
    cudaGetSymbolAddress(&pedge, g_edge);
    cudaGetSymbolAddress(&pwth,  g_wth);
    cudaGetSymbolAddress(&pwtl,  g_wtl);
    cudaGetSymbolAddress(&pw0h,  g_w0h);
    cudaGetSymbolAddress(&pw0l,  g_w0l);
    float* h      = (float*)ph;
    float* h0     = (float*)ph0;
    float* sup    = (float*)psup;
    int*   rowptr = (int*)prp;
    int*   cnt    = (int*)pcnt;
    int2*  edge   = (int2*)pedge;
    __nv_bfloat16* wth = (__nv_bfloat16*)pwth;
    __nv_bfloat16* wtl = (__nv_bfloat16*)pwtl;
    __nv_bfloat16* w0h = (__nv_bfloat16*)pw0h;
    __nv_bfloat16* w0l = (__nv_bfloat16*)pw0l;

    cudaFuncSetAttribute(gemm_mma_kernel,
                         cudaFuncAttributeMaxDynamicSharedMemorySize, GEMM_SMEM);

    // CSR-by-dst build
    zero_cnt_kernel<<<(NN + 255) / 256, 256>>>(cnt);
    hist_kernel    <<<(NE + 255) / 256, 256>>>(edst, cnt);
    scan_kernel    <<<1, 1024>>>(cnt, rowptr);
    scatter_kernel <<<(NE + 255) / 256, 256>>>(esrc, edst, ew, cnt, edge);

    // weight transpose + residual fold + bf16 hi/lo split
    Thetas th;
    for (int i = 0; i < NLAYER; ++i)
        th.t[i] = (float)log(0.5 / (double)(i + 1) + 1.0);
    prep_w_kernel<<<(NLAYER * NH * NH + 255) / 256, 256>>>(w0, convw, w0h, w0l,
                                                           wth, wtl, th);

    dim3 gg(NH / BN, (NN + BM - 1) / BM);   // N-tile fastest for A L2 reuse
    const int sgrid = (NN + 7) / 8;

    // h = h0 = relu(x @ w0 + b0)
    gemm_mma_kernel<<<gg, 256, GEMM_SMEM>>>(x, NN, NF, w0h, w0l, b0, h, h0, 0);

    for (int i = 0; i < NLAYER; ++i) {
        // support = 0.9 * spmm(h) + 0.1 * h0  (two half-feature passes keep the
        // gathered h lines L2-resident)
        spmm_half_kernel<<<sgrid, 256>>>(rowptr, edge, h, h0, sup, 0);
        spmm_half_kernel<<<sgrid, 256>>>(rowptr, edge, h, h0, sup, 32);
        // h = relu(support @ W'_i + h)   (residual folded into W')
        gemm_mma_kernel<<<gg, 256, GEMM_SMEM>>>(sup, NN, NH,
                                                wth + (size_t)i * NH * NH,
                                                wtl + (size_t)i * NH * NH,
                                                nullptr, h, h0, 1);
    }

    // out = sigmoid(h @ w1 + b1)
    fc1_kernel<<<(NN + 7) / 8, 128>>>(h, w1, b1, out);
}

// round 11
// speedup vs baseline: 1.0357x; 1.0357x over previous
#include <cuda_runtime.h>
#include <cuda_bf16.h>
#include <math.h>
#include <stdint.h>

#define NN 100000
#define NE 3200000
#define NF 512
#define NH 256
#define NC 16
#define NLAYER 8

// ---------------- device scratch (allocation-free rule: __device__ globals) ----
__device__ float g_h  [(size_t)NN * NH];
__device__ float g_h0 [(size_t)NN * NH];
__device__ float g_sup[(size_t)NN * NH];
__device__ int   g_rowptr[NN + 1];
__device__ int   g_cnt[NN];
__device__ int2  g_edge[NE];     // packed (src, 0.9*weight bits)
// pre-transposed, bf16 hi/lo split weights:
// conv W' = theta*W + (1-theta)*I  -> [8][N=256][K=256];  fc0 [N=256][K=512]
__device__ __nv_bfloat16 g_wth[(size_t)NLAYER * NH * NH];
__device__ __nv_bfloat16 g_wtl[(size_t)NLAYER * NH * NH];
__device__ __nv_bfloat16 g_w0h[(size_t)NH * NF];
__device__ __nv_bfloat16 g_w0l[(size_t)NH * NF];

struct Thetas { float t[NLAYER]; };

// ---------------- CSR build ---------------------------------------------------
__global__ void zero_cnt_kernel(int* __restrict__ cnt) {
    int i = blockIdx.x * blockDim.x + threadIdx.x;
    if (i < NN) cnt[i] = 0;
}

__global__ void hist_kernel(const int* __restrict__ dst, int* __restrict__ cnt) {
    int e = blockIdx.x * blockDim.x + threadIdx.x;
    if (e < NE) atomicAdd(&cnt[dst[e]], 1);
}

__global__ __launch_bounds__(1024) void scan_kernel(int* __restrict__ cnt,
                                                    int* __restrict__ rowptr) {
    const int tid  = threadIdx.x;
    const int lane = tid & 31;
    const int wid  = tid >> 5;
    __shared__ int wsum[32];
    int carry = 0;
    for (int base = 0; base < NN; base += 1024) {
        int i = base + tid;
        int v = (i < NN) ? cnt[i] : 0;
        int incl = v;
#pragma unroll
        for (int off = 1; off < 32; off <<= 1) {
            int t = __shfl_up_sync(0xffffffffu, incl, off);
            if (lane >= off) incl += t;
        }
        if (lane == 31) wsum[wid] = incl;
        __syncthreads();
        if (wid == 0) {
            int s = wsum[lane];
#pragma unroll
            for (int off = 1; off < 32; off <<= 1) {
                int t = __shfl_up_sync(0xffffffffu, s, off);
                if (lane >= off) s += t;
            }
            wsum[lane] = s;
        }
        __syncthreads();
        int woff = (wid > 0) ? wsum[wid - 1] : 0;
        int excl = carry + woff + (incl - v);
        if (i < NN) { rowptr[i] = excl; cnt[i] = excl; }
        int total = wsum[31];
        __syncthreads();
        carry += total;
    }
    if (tid == 0) rowptr[NN] = carry;
}

__global__ void scatter_kernel(const int* __restrict__ src,
                               const int* __restrict__ dst,
                               const float* __restrict__ w,
                               int* __restrict__ cur,
                               int2* __restrict__ edge) {
    int e = blockIdx.x * blockDim.x + threadIdx.x;
    if (e < NE) {
        int d = dst[e];
        int p = atomicAdd(&cur[d], 1);
        edge[p] = make_int2(src[e], __float_as_int(0.9f * w[e]));
    }
}

// ---------------- weight transpose + residual fold + bf16 hi/lo split ----------
__global__ void prep_w_kernel(const float* __restrict__ w0,
                              const float* __restrict__ convw,
                              __nv_bfloat16* __restrict__ w0h,
                              __nv_bfloat16* __restrict__ w0l,
                              __nv_bfloat16* __restrict__ wth,
                              __nv_bfloat16* __restrict__ wtl,
                              Thetas th) {
    int i = blockIdx.x * blockDim.x + threadIdx.x;
    if (i < NH * NF) {           // w0^T: [n][k], k stride 512
        int n = i >> 9, k = i & 511;
        float f = w0[(size_t)k * NH + n];
        __nv_bfloat16 h = __float2bfloat16(f);
        w0h[i] = h;
        w0l[i] = __float2bfloat16(f - __bfloat162float(h));
    }
    if (i < NLAYER * NH * NH) {  // W'^T: [l][n][k];  W' = theta*W + (1-theta)*I
        int l = i >> 16, nk = i & 65535, n = nk >> 8, k = nk & 255;
        float theta = th.t[l];
        float f = theta * convw[(size_t)l * 65536 + (size_t)k * NH + n];
        if (k == n) f += 1.0f - theta;
        __nv_bfloat16 h = __float2bfloat16(f);
        wth[i] = h;
        wtl[i] = __float2bfloat16(f - __bfloat162float(h));
    }
}

// ---------------- SpMM: warp per row, half features per pass, MLP=8 -----------
__device__ __forceinline__ void fmav(float4& a, float w, const float4& v) {
    a.x = fmaf(w, v.x, a.x); a.y = fmaf(w, v.y, a.y);
    a.z = fmaf(w, v.z, a.z); a.w = fmaf(w, v.w, a.w);
}

__global__ __launch_bounds__(256) void spmm_half_kernel(
    const int* __restrict__ rowptr, const int2* __restrict__ edge,
    const float* __restrict__ h, const float* __restrict__ h0,
    float* __restrict__ sup, int col4) {
    const int warp = threadIdx.x >> 5;
    const int lane = threadIdx.x & 31;
    const int row  = blockIdx.x * 8 + warp;
    if (row >= NN) return;
    int e = rowptr[row];
    const int end = rowptr[row + 1];
    const float4* hp = (const float4*)h + col4 + lane;
    float4 acc = make_float4(0.f, 0.f, 0.f, 0.f);
    for (; e + 8 <= end; e += 8) {
        int2 r[8];
#pragma unroll
        for (int i = 0; i < 8; ++i) r[i] = __ldg(edge + e + i);
        float4 v[8];
#pragma unroll
        for (int i = 0; i < 8; ++i) v[i] = hp[(size_t)(r[i].x * 64)];
#pragma unroll
        for (int i = 0; i < 8; ++i) fmav(acc, __int_as_float(r[i].y), v[i]);
    }
    if (e + 4 <= end) {
        int2 r[4];
#pragma unroll
        for (int i = 0; i < 4; ++i) r[i] = __ldg(edge + e + i);
        float4 v[4];
#pragma unroll
        for (int i = 0; i < 4; ++i) v[i] = hp[(size_t)(r[i].x * 64)];
#pragma unroll
        for (int i = 0; i < 4; ++i) fmav(acc, __int_as_float(r[i].y), v[i]);
        e += 4;
    }
    for (; e < end; ++e) {
        int2 r = __ldg(edge + e);
        fmav(acc, __int_as_float(r.y), hp[(size_t)(r.x * 64)]);
    }
    const size_t oi = (size_t)row * 64 + col4 + lane;
    float4 r = __ldcs((const float4*)h0 + oi);
    float4 o;
    o.x = fmaf(0.1f, r.x, acc.x);
    o.y = fmaf(0.1f, r.y, acc.y);
    o.z = fmaf(0.1f, r.z, acc.z);
    o.w = fmaf(0.1f, r.w, acc.w);
    __stcs((float4*)sup + oi, o);
}

// ---------------- mma.sync bf16 GEMM: 128x128 tile, hi/lo split, prefetched ----
// mode 0: h = h0 = relu(A@B + bias)       (A = x, K = 512)
// mode 1: h = relu(A@B' + h)              (A = sup, K = 256, residual folded in B')
// B pre-transposed K-major bf16: Bh/Bl[n][k], row stride K.
#define BM 128
#define BN 128
#define BKC 64
#define SA_H 0
#define SA_L 16384
#define SB_H 32768
#define SB_L 49152
#define GEMM_SMEM 65536

__device__ __forceinline__ uint32_t smem_u32(const void* p) {
    uint32_t a;
    asm("{ .reg .u64 t; cvta.to.shared.u64 t, %1; cvt.u32.u64 %0, t; }" : "=r"(a) : "l"(p));
    return a;
}

__device__ __forceinline__ void ldsm_x4(uint32_t* r, uint32_t addr) {
    asm volatile("ldmatrix.sync.aligned.m8n8.x4.shared.b16 {%0,%1,%2,%3}, [%4];"
                 : "=r"(r[0]), "=r"(r[1]), "=r"(r[2]), "=r"(r[3]) : "r"(addr));
}
__device__ __forceinline__ void ldsm_x2(uint32_t* r, uint32_t addr) {
    asm volatile("ldmatrix.sync.aligned.m8n8.x2.shared.b16 {%0,%1}, [%2];"
                 : "=r"(r[0]), "=r"(r[1]) : "r"(addr));
}
__device__ __forceinline__ void mma_bf16(float* d, const uint32_t* a, const uint32_t* b) {
    asm volatile("mma.sync.aligned.m16n8k16.row.col.f32.bf16.bf16.f32 "
                 "{%0,%1,%2,%3}, {%4,%5,%6,%7}, {%8,%9}, {%0,%1,%2,%3};"
                 : "+f"(d[0]), "+f"(d[1]), "+f"(d[2]), "+f"(d[3])
                 : "r"(a[0]), "r"(a[1]), "r"(a[2]), "r"(a[3]), "r"(b[0]), "r"(b[1]));
}

__global__ __launch_bounds__(256) void gemm_mma_kernel(
    const float* __restrict__ A, int M, int K,
    const __nv_bfloat16* __restrict__ Bh, const __nv_bfloat16* __restrict__ Bl,
    const float* __restrict__ bias,
    float* __restrict__ hout, float* __restrict__ h0out,
    int mode) {
    extern __shared__ char smem[];
    const uint32_t sb = smem_u32(smem);
    const int tid  = threadIdx.x;
    const int warp = tid >> 5;
    const int lane = tid & 31;
    const int wm = warp & 1;    // M warp: 0..1 -> 64 rows each
    const int wn = warp >> 1;   // N warp: 0..3 -> 32 cols each
    const int rowBase = blockIdx.x * BM;
    const int nBase   = blockIdx.y * BN;

    float acc[4][4][4];
#pragma unroll
    for (int i = 0; i < 4; i++)
#pragma unroll
        for (int j = 0; j < 4; j++)
#pragma unroll
            for (int r = 0; r < 4; r++) acc[i][j][r] = 0.f;

    const int frow = tid >> 3;   // 0..31 (+32*j)
    const int fc8  = tid & 7;    // 8-element unit within 64-wide chunk

    // prefetch registers for one chunk
    float4 pa0[4], pa1[4];
    uint4  pbh[4], pbl[4];

    auto load_chunk = [&](int kb) {
#pragma unroll
        for (int j = 0; j < 4; ++j) {
            int grow = rowBase + frow + 32 * j;
            pa0[j] = make_float4(0.f, 0.f, 0.f, 0.f);
            pa1[j] = pa0[j];
            if (grow < M) {
                const float* ap = A + (size_t)grow * K + kb + fc8 * 8;
                pa0[j] = *(const float4*)ap;
                pa1[j] = *(const float4*)(ap + 4);
            }
            size_t gi = (size_t)(nBase + frow + 32 * j) * K + kb + fc8 * 8;
            pbh[j] = *(const uint4*)(Bh + gi);
            pbl[j] = *(const uint4*)(Bl + gi);
        }
    };

    auto store_chunk = [&]() {
#pragma unroll
        for (int j = 0; j < 4; ++j) {
            int row = frow + 32 * j;
            float4 v0 = pa0[j], v1 = pa1[j];
            __nv_bfloat162 h01 = __floats2bfloat162_rn(v0.x, v0.y);
            __nv_bfloat162 h23 = __floats2bfloat162_rn(v0.z, v0.w);
            __nv_bfloat162 h45 = __floats2bfloat162_rn(v1.x, v1.y);
            __nv_bfloat162 h67 = __floats2bfloat162_rn(v1.z, v1.w);
            float2 f01 = __bfloat1622float2(h01);
            float2 f23 = __bfloat1622float2(h23);
            float2 f45 = __bfloat1622float2(h45);
            float2 f67 = __bfloat1622float2(h67);
            __nv_bfloat162 l01 = __floats2bfloat162_rn(v0.x - f01.x, v0.y - f01.y);
            __nv_bfloat162 l23 = __floats2bfloat162_rn(v0.z - f23.x, v0.w - f23.y);
            __nv_bfloat162 l45 = __floats2bfloat162_rn(v1.x - f45.x, v1.y - f45.y);
            __nv_bfloat162 l67 = __floats2bfloat162_rn(v1.z - f67.x, v1.w - f67.y);
            uint32_t off = (uint32_t)(row * 128 + ((fc8 ^ (row & 7)) << 4));
            uint4 uh, ul;
            uh.x = *(uint32_t*)&h01; uh.y = *(uint32_t*)&h23;
            uh.z = *(uint32_t*)&h45; uh.w = *(uint32_t*)&h67;
            ul.x = *(uint32_t*)&l01; ul.y = *(uint32_t*)&l23;
            ul.z = *(uint32_t*)&l45; ul.w = *(uint32_t*)&l67;
            *(uint4*)(smem + SA_H + off) = uh;
            *(uint4*)(smem + SA_L + off) = ul;
            *(uint4*)(smem + SB_H + off) = pbh[j];
            *(uint4*)(smem + SB_L + off) = pbl[j];
        }
    };

    const int nch = K / BKC;
    load_chunk(0);
    store_chunk();
    __syncthreads();

    for (int ch = 0; ch < nch; ++ch) {
        const bool more = (ch + 1 < nch);
        if (more) load_chunk((ch + 1) * BKC);  // LDGs fly under the MMAs below

        // ---- compute: 4 k16 steps over current smem ----
#pragma unroll
        for (int ks = 0; ks < 4; ++ks) {
            const int u0 = ks * 2;
            uint32_t ah[4][4], al[4][4], bh[4][2], bl[4][2];
#pragma unroll
            for (int mt = 0; mt < 4; ++mt) {
                int row  = wm * 64 + mt * 16 + (lane & 15);
                int unit = u0 + (lane >> 4);
                uint32_t off = (uint32_t)(row * 128 + ((unit ^ (row & 7)) << 4));
                ldsm_x4(ah[mt], sb + SA_H + off);
                ldsm_x4(al[mt], sb + SA_L + off);
            }
#pragma unroll
            for (int nt = 0; nt < 4; ++nt) {
                int n    = wn * 32 + nt * 8 + (lane & 7);
                int unit = u0 + ((lane >> 3) & 1);
                uint32_t off = (uint32_t)(n * 128 + ((unit ^ (n & 7)) << 4));
                ldsm_x2(bh[nt], sb + SB_H + off);
                ldsm_x2(bl[nt], sb + SB_L + off);
            }
#pragma unroll
            for (int mt = 0; mt < 4; ++mt)
#pragma unroll
                for (int nt = 0; nt < 4; ++nt) {
                    mma_bf16(acc[mt][nt], ah[mt], bh[nt]);
                    mma_bf16(acc[mt][nt], ah[mt], bl[nt]);
                    mma_bf16(acc[mt][nt], al[mt], bh[nt]);
                }
        }
        __syncthreads();
        if (more) {
            store_chunk();
            __syncthreads();
        }
    }

    // ---- epilogue ----
    const int r0 = rowBase + wm * 64 + (lane >> 2);
    const int c0 = nBase + wn * 32 + 2 * (lane & 3);
#pragma unroll
    for (int mt = 0; mt < 4; ++mt) {
#pragma unroll
        for (int half = 0; half < 2; ++half) {
            int grow = r0 + mt * 16 + half * 8;
            if (grow >= M) continue;
#pragma unroll
            for (int nt = 0; nt < 4; ++nt) {
                float d0 = acc[mt][nt][half * 2 + 0];
                float d1 = acc[mt][nt][half * 2 + 1];
                int gc = c0 + nt * 8;
                size_t gi = (size_t)grow * NH + gc;
                if (mode == 0) {
                    float v0 = fmaxf(d0 + __ldg(&bias[gc]),     0.f);
                    float v1 = fmaxf(d1 + __ldg(&bias[gc + 1]), 0.f);
                    float2 v = make_float2(v0, v1);
                    *(float2*)(hout  + gi) = v;
                    *(float2*)(h0out + gi) = v;
                } else {
                    float2 ho = *(const float2*)(hout + gi);
                    float v0 = fmaxf(d0 + ho.x, 0.f);
                    float v1 = fmaxf(d1 + ho.y, 0.f);
                    *(float2*)(hout + gi) = make_float2(v0, v1);
                }
            }
        }
    }
}

// ---------------- final fc + sigmoid ------------------------------------------
__global__ __launch_bounds__(128) void fc1_kernel(const float* __restrict__ h,
                                                  const float* __restrict__ w1,
                                                  const float* __restrict__ b1,
                                                  float* __restrict__ out) {
    __shared__ float ws[NH * NC];
    __shared__ float bs[NC];
    const int tid = threadIdx.x;
    for (int i = tid; i < NH * NC; i += 128) ws[i] = w1[i];
    if (tid < NC) bs[tid] = b1[tid];
    __syncthreads();
    const int col = tid & 15;
    const int r   = tid >> 4;
    const int row = blockIdx.x * 8 + r;
    if (row >= NN) return;
    const float* hr = h + (size_t)row * NH;
    float acc = 0.f;
#pragma unroll 4
    for (int k = 0; k < NH; k += 4) {
        float4 hv = *(const float4*)(hr + k);
        acc = fmaf(hv.x, ws[(k + 0) * NC + col], acc);
        acc = fmaf(hv.y, ws[(k + 1) * NC + col], acc);
        acc = fmaf(hv.z, ws[(k + 2) * NC + col], acc);
        acc = fmaf(hv.w, ws[(k + 3) * NC + col], acc);
    }
    acc += bs[col];
    out[(size_t)row * NC + col] = 1.0f / (1.0f + expf(-acc));
}

// ---------------- launch -------------------------------------------------------
extern "C" void kernel_launch(void* const* d_in, const int* in_sizes, int n_in,
                              void* d_out, int out_size) {
    const float* x     = (const float*)d_in[0];
    const int*   esrc  = (const int*)  d_in[1];
    const int*   edst  = (const int*)  d_in[2];
    const float* ew    = (const float*)d_in[3];
    const float* w0    = (const float*)d_in[4];
    const float* b0    = (const float*)d_in[5];
    const float* convw = (const float*)d_in[6];
    const float* w1    = (const float*)d_in[7];
    const float* b1    = (const float*)d_in[8];
    float* out = (float*)d_out;

    void *ph, *ph0, *psup, *prp, *pcnt, *pedge;
    void *pwth, *pwtl, *pw0h, *pw0l;
    cudaGetSymbolAddress(&ph,    g_h);
    cudaGetSymbolAddress(&ph0,   g_h0);
    cudaGetSymbolAddress(&psup,  g_sup);
    cudaGetSymbolAddress(&prp,   g_rowptr);
    cudaGetSymbolAddress(&pcnt,  g_cnt);
    cudaGetSymbolAddress(&pedge, g_edge);
    cudaGetSymbolAddress(&pwth,  g_wth);
    cudaGetSymbolAddress(&pwtl,  g_wtl);
    cudaGetSymbolAddress(&pw0h,  g_w0h);
    cudaGetSymbolAddress(&pw0l,  g_w0l);
    float* h      = (float*)ph;
    float* h0     = (float*)ph0;
    float* sup    = (float*)psup;
    int*   rowptr = (int*)prp;
    int*   cnt    = (int*)pcnt;
    int2*  edge   = (int2*)pedge;
    __nv_bfloat16* wth = (__nv_bfloat16*)pwth;
    __nv_bfloat16* wtl = (__nv_bfloat16*)pwtl;
    __nv_bfloat16* w0h = (__nv_bfloat16*)pw0h;
    __nv_bfloat16* w0l = (__nv_bfloat16*)pw0l;

    cudaFuncSetAttribute(gemm_mma_kernel,
                         cudaFuncAttributeMaxDynamicSharedMemorySize, GEMM_SMEM);

    // CSR-by-dst build
    zero_cnt_kernel<<<(NN + 255) / 256, 256>>>(cnt);
    hist_kernel    <<<(NE + 255) / 256, 256>>>(edst, cnt);
    scan_kernel    <<<1, 1024>>>(cnt, rowptr);
    scatter_kernel <<<(NE + 255) / 256, 256>>>(esrc, edst, ew, cnt, edge);

    // weight transpose + residual fold + bf16 hi/lo split
    Thetas th;
    for (int i = 0; i < NLAYER; ++i)
        th.t[i] = (float)log(0.5 / (double)(i + 1) + 1.0);
    prep_w_kernel<<<(NLAYER * NH * NH + 255) / 256, 256>>>(w0, convw, w0h, w0l,
                                                           wth, wtl, th);

    dim3 gg((NN + BM - 1) / BM, NH / BN);
    const int sgrid = (NN + 7) / 8;

    // h = h0 = relu(x @ w0 + b0)
    gemm_mma_kernel<<<gg, 256, GEMM_SMEM>>>(x, NN, NF, w0h, w0l, b0, h, h0, 0);

    for (int i = 0; i < NLAYER; ++i) {
        // support = spmm_{0.9w}(h) + 0.1 * h0  (two half-feature passes keep the
        // gathered h lines L2-resident; 0.9 folded into edge weights)
        spmm_half_kernel<<<sgrid, 256>>>(rowptr, edge, h, h0, sup, 0);
        spmm_half_kernel<<<sgrid, 256>>>(rowptr, edge, h, h0, sup, 32);
        // h = relu(support @ W'_i + h)   (residual folded into W')
        gemm_mma_kernel<<<gg, 256, GEMM_SMEM>>>(sup, NN, NH,
                                                wth + (size_t)i * NH * NH,
                                                wtl + (size_t)i * NH * NH,
                                                nullptr, h, h0, 1);
    }

    // out = sigmoid(h @ w1 + b1)
    fc1_kernel<<<(NN + 7) / 8, 128>>>(h, w1, b1, out);
}

// round 12
// speedup vs baseline: 1.0464x; 1.0103x over previous
#include <cuda_runtime.h>
#include <cuda_bf16.h>
#include <math.h>
#include <stdint.h>

#define NN 100000
#define NE 3200000
#define NF 512
#define NH 256
#define NC 16
#define NLAYER 8

// ---------------- device scratch (allocation-free rule: __device__ globals) ----
__device__ float g_h  [(size_t)NN * NH];
__device__ float g_h0 [(size_t)NN * NH];
__device__ float g_sup[(size_t)NN * NH];
__device__ int   g_rowptr[NN + 1];
__device__ int   g_cnt[NN];
__device__ int2  g_edge[NE];     // packed (src, 0.9*weight bits)
// pre-transposed, bf16 hi/lo split weights:
// conv W' = theta*W + (1-theta)*I  -> [8][N=256][K=256];  fc0 [N=256][K=512]
__device__ __nv_bfloat16 g_wth[(size_t)NLAYER * NH * NH];
__device__ __nv_bfloat16 g_wtl[(size_t)NLAYER * NH * NH];
__device__ __nv_bfloat16 g_w0h[(size_t)NH * NF];
__device__ __nv_bfloat16 g_w0l[(size_t)NH * NF];

struct Thetas { float t[NLAYER]; };

// ---------------- CSR build ---------------------------------------------------
__global__ void zero_cnt_kernel(int* __restrict__ cnt) {
    int i = blockIdx.x * blockDim.x + threadIdx.x;
    if (i < NN) cnt[i] = 0;
}

__global__ void hist_kernel(const int* __restrict__ dst, int* __restrict__ cnt) {
    int e = blockIdx.x * blockDim.x + threadIdx.x;
    if (e < NE) atomicAdd(&cnt[dst[e]], 1);
}

__global__ __launch_bounds__(1024) void scan_kernel(int* __restrict__ cnt,
                                                    int* __restrict__ rowptr) {
    const int tid  = threadIdx.x;
    const int lane = tid & 31;
    const int wid  = tid >> 5;
    __shared__ int wsum[32];
    int carry = 0;
    for (int base = 0; base < NN; base += 1024) {
        int i = base + tid;
        int v = (i < NN) ? cnt[i] : 0;
        int incl = v;
#pragma unroll
        for (int off = 1; off < 32; off <<= 1) {
            int t = __shfl_up_sync(0xffffffffu, incl, off);
            if (lane >= off) incl += t;
        }
        if (lane == 31) wsum[wid] = incl;
        __syncthreads();
        if (wid == 0) {
            int s = wsum[lane];
#pragma unroll
            for (int off = 1; off < 32; off <<= 1) {
                int t = __shfl_up_sync(0xffffffffu, s, off);
                if (lane >= off) s += t;
            }
            wsum[lane] = s;
        }
        __syncthreads();
        int woff = (wid > 0) ? wsum[wid - 1] : 0;
        int excl = carry + woff + (incl - v);
        if (i < NN) { rowptr[i] = excl; cnt[i] = excl; }
        int total = wsum[31];
        __syncthreads();
        carry += total;
    }
    if (tid == 0) rowptr[NN] = carry;
}

__global__ void scatter_kernel(const int* __restrict__ src,
                               const int* __restrict__ dst,
                               const float* __restrict__ w,
                               int* __restrict__ cur,
                               int2* __restrict__ edge) {
    int e = blockIdx.x * blockDim.x + threadIdx.x;
    if (e < NE) {
        int d = dst[e];
        int p = atomicAdd(&cur[d], 1);
        edge[p] = make_int2(src[e], __float_as_int(0.9f * w[e]));
    }
}

// ---------------- weight transpose + residual fold + bf16 hi/lo split ----------
__global__ void prep_w_kernel(const float* __restrict__ w0,
                              const float* __restrict__ convw,
                              __nv_bfloat16* __restrict__ w0h,
                              __nv_bfloat16* __restrict__ w0l,
                              __nv_bfloat16* __restrict__ wth,
                              __nv_bfloat16* __restrict__ wtl,
                              Thetas th) {
    int i = blockIdx.x * blockDim.x + threadIdx.x;
    if (i < NH * NF) {           // w0^T: [n][k], k stride 512
        int n = i >> 9, k = i & 511;
        float f = w0[(size_t)k * NH + n];
        __nv_bfloat16 h = __float2bfloat16(f);
        w0h[i] = h;
        w0l[i] = __float2bfloat16(f - __bfloat162float(h));
    }
    if (i < NLAYER * NH * NH) {  // W'^T: [l][n][k];  W' = theta*W + (1-theta)*I
        int l = i >> 16, nk = i & 65535, n = nk >> 8, k = nk & 255;
        float theta = th.t[l];
        float f = theta * convw[(size_t)l * 65536 + (size_t)k * NH + n];
        if (k == n) f += 1.0f - theta;
        __nv_bfloat16 h = __float2bfloat16(f);
        wth[i] = h;
        wtl[i] = __float2bfloat16(f - __bfloat162float(h));
    }
}

// ---------------- SpMM: warp per row, half features per pass, MLP=8 -----------
__device__ __forceinline__ void fmav(float4& a, float w, const float4& v) {
    a.x = fmaf(w, v.x, a.x); a.y = fmaf(w, v.y, a.y);
    a.z = fmaf(w, v.z, a.z); a.w = fmaf(w, v.w, a.w);
}

__global__ __launch_bounds__(256) void spmm_half_kernel(
    const int* __restrict__ rowptr, const int2* __restrict__ edge,
    const float* __restrict__ h, const float* __restrict__ h0,
    float* __restrict__ sup, int col4) {
    const int warp = threadIdx.x >> 5;
    const int lane = threadIdx.x & 31;
    const int row  = blockIdx.x * 8 + warp;
    if (row >= NN) return;
    int e = rowptr[row];
    const int end = rowptr[row + 1];
    const float4* hp = (const float4*)h + col4 + lane;
    float4 acc = make_float4(0.f, 0.f, 0.f, 0.f);
    for (; e + 8 <= end; e += 8) {
        int2 r[8];
#pragma unroll
        for (int i = 0; i < 8; ++i) r[i] = __ldg(edge + e + i);
        float4 v[8];
#pragma unroll
        for (int i = 0; i < 8; ++i) v[i] = hp[(size_t)(r[i].x * 64)];
#pragma unroll
        for (int i = 0; i < 8; ++i) fmav(acc, __int_as_float(r[i].y), v[i]);
    }
    if (e + 4 <= end) {
        int2 r[4];
#pragma unroll
        for (int i = 0; i < 4; ++i) r[i] = __ldg(edge + e + i);
        float4 v[4];
#pragma unroll
        for (int i = 0; i < 4; ++i) v[i] = hp[(size_t)(r[i].x * 64)];
#pragma unroll
        for (int i = 0; i < 4; ++i) fmav(acc, __int_as_float(r[i].y), v[i]);
        e += 4;
    }
    for (; e < end; ++e) {
        int2 r = __ldg(edge + e);
        fmav(acc, __int_as_float(r.y), hp[(size_t)(r.x * 64)]);
    }
    const size_t oi = (size_t)row * 64 + col4 + lane;
    float4 r = __ldcs((const float4*)h0 + oi);
    float4 o;
    o.x = fmaf(0.1f, r.x, acc.x);
    o.y = fmaf(0.1f, r.y, acc.y);
    o.z = fmaf(0.1f, r.z, acc.z);
    o.w = fmaf(0.1f, r.w, acc.w);
    __stcs((float4*)sup + oi, o);
}

// ---------------- mma.sync bf16 GEMM: 128x128 tile, hi/lo split, prefetched ----
// mode 0: h = h0 = relu(A@B + bias)       (A = x, K = 512)
// mode 1: h = relu(A@B' + h)              (A = sup, K = 256, residual folded in B')
// B pre-transposed K-major bf16: Bh/Bl[n][k], row stride K.
#define BM 128
#define BN 128
#define BKC 64
#define SA_H 0
#define SA_L 16384
#define SB_H 32768
#define SB_L 49152
#define GEMM_SMEM 65536

__device__ __forceinline__ uint32_t smem_u32(const void* p) {
    uint32_t a;
    asm("{ .reg .u64 t; cvta.to.shared.u64 t, %1; cvt.u32.u64 %0, t; }" : "=r"(a) : "l"(p));
    return a;
}

__device__ __forceinline__ void ldsm_x4(uint32_t* r, uint32_t addr) {
    asm volatile("ldmatrix.sync.aligned.m8n8.x4.shared.b16 {%0,%1,%2,%3}, [%4];"
                 : "=r"(r[0]), "=r"(r[1]), "=r"(r[2]), "=r"(r[3]) : "r"(addr));
}
__device__ __forceinline__ void ldsm_x2(uint32_t* r, uint32_t addr) {
    asm volatile("ldmatrix.sync.aligned.m8n8.x2.shared.b16 {%0,%1}, [%2];"
                 : "=r"(r[0]), "=r"(r[1]) : "r"(addr));
}
__device__ __forceinline__ void mma_bf16(float* d, const uint32_t* a, const uint32_t* b) {
    asm volatile("mma.sync.aligned.m16n8k16.row.col.f32.bf16.bf16.f32 "
                 "{%0,%1,%2,%3}, {%4,%5,%6,%7}, {%8,%9}, {%0,%1,%2,%3};"
                 : "+f"(d[0]), "+f"(d[1]), "+f"(d[2]), "+f"(d[3])
                 : "r"(a[0]), "r"(a[1]), "r"(a[2]), "r"(a[3]), "r"(b[0]), "r"(b[1]));
}

__global__ __launch_bounds__(256) void gemm_mma_kernel(
    const float* __restrict__ A, int M, int K,
    const __nv_bfloat16* __restrict__ Bh, const __nv_bfloat16* __restrict__ Bl,
    const float* __restrict__ bias,
    float* __restrict__ hout, float* __restrict__ h0out,
    int mode) {
    extern __shared__ char smem[];
    const uint32_t sb = smem_u32(smem);
    const int tid  = threadIdx.x;
    const int warp = tid >> 5;
    const int lane = tid & 31;
    const int wm = warp & 1;    // M warp: 0..1 -> 64 rows each
    const int wn = warp >> 1;   // N warp: 0..3 -> 32 cols each
    const int rowBase = blockIdx.x * BM;
    const int nBase   = blockIdx.y * BN;

    float acc[4][4][4];
#pragma unroll
    for (int i = 0; i < 4; i++)
#pragma unroll
        for (int j = 0; j < 4; j++)
#pragma unroll
            for (int r = 0; r < 4; r++) acc[i][j][r] = 0.f;

    const int frow = tid >> 3;   // 0..31 (+32*j)
    const int fc8  = tid & 7;    // 8-element unit within 64-wide chunk

    // prefetch registers for one chunk
    float4 pa0[4], pa1[4];
    uint4  pbh[4], pbl[4];

    auto load_chunk = [&](int kb) {
#pragma unroll
        for (int j = 0; j < 4; ++j) {
            int grow = rowBase + frow + 32 * j;
            pa0[j] = make_float4(0.f, 0.f, 0.f, 0.f);
            pa1[j] = pa0[j];
            if (grow < M) {
                const float* ap = A + (size_t)grow * K + kb + fc8 * 8;
                pa0[j] = *(const float4*)ap;
                pa1[j] = *(const float4*)(ap + 4);
            }
            size_t gi = (size_t)(nBase + frow + 32 * j) * K + kb + fc8 * 8;
            pbh[j] = *(const uint4*)(Bh + gi);
            pbl[j] = *(const uint4*)(Bl + gi);
        }
    };

    auto store_chunk = [&]() {
#pragma unroll
        for (int j = 0; j < 4; ++j) {
            int row = frow + 32 * j;
            float4 v0 = pa0[j], v1 = pa1[j];
            __nv_bfloat162 h01 = __floats2bfloat162_rn(v0.x, v0.y);
            __nv_bfloat162 h23 = __floats2bfloat162_rn(v0.z, v0.w);
            __nv_bfloat162 h45 = __floats2bfloat162_rn(v1.x, v1.y);
            __nv_bfloat162 h67 = __floats2bfloat162_rn(v1.z, v1.w);
            float2 f01 = __bfloat1622float2(h01);
            float2 f23 = __bfloat1622float2(h23);
            float2 f45 = __bfloat1622float2(h45);
            float2 f67 = __bfloat1622float2(h67);
            __nv_bfloat162 l01 = __floats2bfloat162_rn(v0.x - f01.x, v0.y - f01.y);
            __nv_bfloat162 l23 = __floats2bfloat162_rn(v0.z - f23.x, v0.w - f23.y);
            __nv_bfloat162 l45 = __floats2bfloat162_rn(v1.x - f45.x, v1.y - f45.y);
            __nv_bfloat162 l67 = __floats2bfloat162_rn(v1.z - f67.x, v1.w - f67.y);
            uint32_t off = (uint32_t)(row * 128 + ((fc8 ^ (row & 7)) << 4));
            uint4 uh, ul;
            uh.x = *(uint32_t*)&h01; uh.y = *(uint32_t*)&h23;
            uh.z = *(uint32_t*)&h45; uh.w = *(uint32_t*)&h67;
            ul.x = *(uint32_t*)&l01; ul.y = *(uint32_t*)&l23;
            ul.z = *(uint32_t*)&l45; ul.w = *(uint32_t*)&l67;
            *(uint4*)(smem + SA_H + off) = uh;
            *(uint4*)(smem + SA_L + off) = ul;
            *(uint4*)(smem + SB_H + off) = pbh[j];
            *(uint4*)(smem + SB_L + off) = pbl[j];
        }
    };

    const int nch = K / BKC;
    load_chunk(0);
    store_chunk();
    __syncthreads();

    for (int ch = 0; ch < nch; ++ch) {
        const bool more = (ch + 1 < nch);
        if (more) load_chunk((ch + 1) * BKC);  // LDGs fly under the MMAs below

        // ---- compute: 4 k16 steps over current smem ----
#pragma unroll
        for (int ks = 0; ks < 4; ++ks) {
            const int u0 = ks * 2;
            uint32_t ah[4][4], al[4][4], bh[4][2], bl[4][2];
#pragma unroll
            for (int mt = 0; mt < 4; ++mt) {
                int row  = wm * 64 + mt * 16 + (lane & 15);
                int unit = u0 + (lane >> 4);
                uint32_t off = (uint32_t)(row * 128 + ((unit ^ (row & 7)) << 4));
                ldsm_x4(ah[mt], sb + SA_H + off);
                ldsm_x4(al[mt], sb + SA_L + off);
            }
#pragma unroll
            for (int nt = 0; nt < 4; ++nt) {
                int n    = wn * 32 + nt * 8 + (lane & 7);
                int unit = u0 + ((lane >> 3) & 1);
                uint32_t off = (uint32_t)(n * 128 + ((unit ^ (n & 7)) << 4));
                ldsm_x2(bh[nt], sb + SB_H + off);
                ldsm_x2(bl[nt], sb + SB_L + off);
            }
#pragma unroll
            for (int mt = 0; mt < 4; ++mt)
#pragma unroll
                for (int nt = 0; nt < 4; ++nt) {
                    mma_bf16(acc[mt][nt], ah[mt], bh[nt]);
                    mma_bf16(acc[mt][nt], ah[mt], bl[nt]);
                    mma_bf16(acc[mt][nt], al[mt], bh[nt]);
                }
        }
        __syncthreads();
        if (more) {
            store_chunk();
            __syncthreads();
        }
    }

    // ---- epilogue ----
    const int r0 = rowBase + wm * 64 + (lane >> 2);
    const int c0 = nBase + wn * 32 + 2 * (lane & 3);
#pragma unroll
    for (int mt = 0; mt < 4; ++mt) {
#pragma unroll
        for (int half = 0; half < 2; ++half) {
            int grow = r0 + mt * 16 + half * 8;
            if (grow >= M) continue;
#pragma unroll
            for (int nt = 0; nt < 4; ++nt) {
                float d0 = acc[mt][nt][half * 2 + 0];
                float d1 = acc[mt][nt][half * 2 + 1];
                int gc = c0 + nt * 8;
                size_t gi = (size_t)grow * NH + gc;
                if (mode == 0) {
                    float v0 = fmaxf(d0 + __ldg(&bias[gc]),     0.f);
                    float v1 = fmaxf(d1 + __ldg(&bias[gc + 1]), 0.f);
                    float2 v = make_float2(v0, v1);
                    *(float2*)(hout  + gi) = v;
                    *(float2*)(h0out + gi) = v;
                } else {
                    float2 ho = *(const float2*)(hout + gi);
                    float v0 = fmaxf(d0 + ho.x, 0.f);
                    float v1 = fmaxf(d1 + ho.y, 0.f);
                    *(float2*)(hout + gi) = make_float2(v0, v1);
                }
            }
        }
    }
}

// ---------------- final fc + sigmoid ------------------------------------------
__global__ __launch_bounds__(128) void fc1_kernel(const float* __restrict__ h,
                                                  const float* __restrict__ w1,
                                                  const float* __restrict__ b1,
                                                  float* __restrict__ out) {
    __shared__ float ws[NH * NC];
    __shared__ float bs[NC];
    const int tid = threadIdx.x;
    for (int i = tid; i < NH * NC; i += 128) ws[i] = w1[i];
    if (tid < NC) bs[tid] = b1[tid];
    __syncthreads();
    const int col = tid & 15;
    const int r   = tid >> 4;
    const int row = blockIdx.x * 8 + r;
    if (row >= NN) return;
    const float* hr = h + (size_t)row * NH;
    float acc = 0.f;
#pragma unroll 4
    for (int k = 0; k < NH; k += 4) {
        float4 hv = *(const float4*)(hr + k);
        acc = fmaf(hv.x, ws[(k + 0) * NC + col], acc);
        acc = fmaf(hv.y, ws[(k + 1) * NC + col], acc);
        acc = fmaf(hv.z, ws[(k + 2) * NC + col], acc);
        acc = fmaf(hv.w, ws[(k + 3) * NC + col], acc);
    }
    acc += bs[col];
    out[(size_t)row * NC + col] = 1.0f / (1.0f + expf(-acc));
}

// ---------------- launch -------------------------------------------------------
extern "C" void kernel_launch(void* const* d_in, const int* in_sizes, int n_in,
                              void* d_out, int out_size) {
    const float* x     = (const float*)d_in[0];
    const int*   esrc  = (const int*)  d_in[1];
    const int*   edst  = (const int*)  d_in[2];
    const float* ew    = (const float*)d_in[3];
    const float* w0    = (const float*)d_in[4];
    const float* b0    = (const float*)d_in[5];
    const float* convw = (const float*)d_in[6];
    const float* w1    = (const float*)d_in[7];
    const float* b1    = (const float*)d_in[8];
    float* out = (float*)d_out;

    void *ph, *ph0, *psup, *prp, *pcnt, *pedge;
    void *pwth, *pwtl, *pw0h, *pw0l;
    cudaGetSymbolAddress(&ph,    g_h);
    cudaGetSymbolAddress(&ph0,   g_h0);
    cudaGetSymbolAddress(&psup,  g_sup);
    cudaGetSymbolAddress(&prp,   g_rowptr);
    cudaGetSymbolAddress(&pcnt,  g_cnt);
    cudaGetSymbolAddress(&pedge, g_edge);
    cudaGetSymbolAddress(&pwth,  g_wth);
    cudaGetSymbolAddress(&pwtl,  g_wtl);
    cudaGetSymbolAddress(&pw0h,  g_w0h);
    cudaGetSymbolAddress(&pw0l,  g_w0l);
    float* h      = (float*)ph;
    float* h0     = (float*)ph0;
    float* sup    = (float*)psup;
    int*   rowptr = (int*)prp;
    int*   cnt    = (int*)pcnt;
    int2*  edge   = (int2*)pedge;
    __nv_bfloat16* wth = (__nv_bfloat16*)pwth;
    __nv_bfloat16* wtl = (__nv_bfloat16*)pwtl;
    __nv_bfloat16* w0h = (__nv_bfloat16*)pw0h;
    __nv_bfloat16* w0l = (__nv_bfloat16*)pw0l;

    cudaFuncSetAttribute(gemm_mma_kernel,
                         cudaFuncAttributeMaxDynamicSharedMemorySize, GEMM_SMEM);

    // CSR-by-dst build
    zero_cnt_kernel<<<(NN + 255) / 256, 256>>>(cnt);
    hist_kernel    <<<(NE + 255) / 256, 256>>>(edst, cnt);
    scan_kernel    <<<1, 1024>>>(cnt, rowptr);
    scatter_kernel <<<(NE + 255) / 256, 256>>>(esrc, edst, ew, cnt, edge);

    // weight transpose + residual fold + bf16 hi/lo split
    Thetas th;
    for (int i = 0; i < NLAYER; ++i)
        th.t[i] = (float)log(0.5 / (double)(i + 1) + 1.0);
    prep_w_kernel<<<(NLAYER * NH * NH + 255) / 256, 256>>>(w0, convw, w0h, w0l,
                                                           wth, wtl, th);

    dim3 gg((NN + BM - 1) / BM, NH / BN);
    const int sgrid = (NN + 7) / 8;

    // h = h0 = relu(x @ w0 + b0)
    gemm_mma_kernel<<<gg, 256, GEMM_SMEM>>>(x, NN, NF, w0h, w0l, b0, h, h0, 0);

    for (int i = 0; i < NLAYER; ++i) {
        // support = spmm_{0.9w}(h) + 0.1 * h0  (two half-feature passes keep the
        // gathered h lines L2-resident; 0.9 folded into edge weights)
        spmm_half_kernel<<<sgrid, 256>>>(rowptr, edge, h, h0, sup, 0);
        spmm_half_kernel<<<sgrid, 256>>>(rowptr, edge, h, h0, sup, 32);
        // h = relu(support @ W'_i + h)   (residual folded into W')
        gemm_mma_kernel<<<gg, 256, GEMM_SMEM>>>(sup, NN, NH,
                                                wth + (size_t)i * NH * NH,
                                                wtl + (size_t)i * NH * NH,
                                                nullptr, h, h0, 1);
    }

    // out = sigmoid(h @ w1 + b1)
    fc1_kernel<<<(NN + 7) / 8, 128>>>(h, w1, b1, out);
}